// round 3
// baseline (speedup 1.0000x reference)
#include <cuda_runtime.h>
#include <cstdint>
#include <cstddef>

typedef unsigned long long ull;

// ---------------------------------------------------------------------------
// f32x2 packed-math + fast activation helpers (sm_103a)
// ---------------------------------------------------------------------------
__device__ __forceinline__ ull pack2(float lo, float hi) {
    ull r;
    asm("mov.b64 %0, {%1, %2};" : "=l"(r) : "f"(lo), "f"(hi));
    return r;
}
__device__ __forceinline__ void unpack2(ull v, float& lo, float& hi) {
    asm("mov.b64 {%0, %1}, %2;" : "=f"(lo), "=f"(hi) : "l"(v));
}
__device__ __forceinline__ ull fma2(ull a, ull b, ull c) {
    ull d;
    asm("fma.rn.f32x2 %0, %1, %2, %3;" : "=l"(d) : "l"(a), "l"(b), "l"(c));
    return d;
}
__device__ __forceinline__ ull add2(ull a, ull b) {
    ull d;
    asm("add.rn.f32x2 %0, %1, %2;" : "=l"(d) : "l"(a), "l"(b));
    return d;
}
__device__ __forceinline__ float tanh_fast(float x) {
    float y;
    asm("tanh.approx.f32 %0, %1;" : "=f"(y) : "f"(x));
    return y;
}
__device__ __forceinline__ float sig_fast(float x) {
    return fmaf(0.5f, tanh_fast(0.5f * x), 0.5f);
}

// ---------------------------------------------------------------------------
// Problem constants
// ---------------------------------------------------------------------------
#define B_    4
#define CIN_  3
#define T_    32
#define H_    64
#define W_    64
#define COUT_ 64
#define NCH_  256           // 4*COUT gate channels
#define HW_   4096
#define KTAPS 54

// Pre-packed weight pairs: [128 channel-pairs][54 taps] of {w[2p],w[2p+1]}
__device__ ull g_Wpk[128 * KTAPS];
__device__ ull g_Bpk[128];

__global__ void __launch_bounds__(256)
pack_kernel(const float* __restrict__ Wc, const float* __restrict__ bconv) {
    int i = blockIdx.x * 256 + threadIdx.x;
    if (i < 128 * KTAPS) {
        int p = i / KTAPS;
        int k = i - p * KTAPS;
        g_Wpk[i] = pack2(Wc[(2 * p) * KTAPS + k], Wc[(2 * p + 1) * KTAPS + k]);
    }
    if (i < 128) g_Bpk[i] = pack2(bconv[2 * i], bconv[2 * i + 1]);
}

// ---------------------------------------------------------------------------
// Fused conv + QRNN kernel.
// CTA = 8x8 pixel tile x all 256 gate channels, loops over t internally.
// 256 threads: conv role = (pixel 0..63, channel-slice 0..3 of 32 pairs),
//              recur role = (pixel 0..63, 16 couts).
// ---------------------------------------------------------------------------
#define SM_WS_ULL   (128 * KTAPS)          // 6912 ull  = 55296 B
#define SM_WS_OFF   0
#define SM_BS_OFF   (SM_WS_ULL * 8)        // 55296
#define SM_GSM_OFF  (SM_BS_OFF + 128 * 8)  // 56320  : gates [256][64] f32 = 64 KB
#define SM_PSM_OFF  (SM_GSM_OFF + 65536)   // 121856 : peephole [3][64][64] f32 = 48 KB
#define SM_HSM_OFF  (SM_PSM_OFF + 49152)   // 171008 : halo [3][10][12] f32 = 1440 B
#define SM_TOTAL    (SM_HSM_OFF + 1440)    // 172448 B

__global__ void __launch_bounds__(256, 1)
fused_kernel(const float* __restrict__ X,
             const float* __restrict__ Wci, const float* __restrict__ Wcf,
             const float* __restrict__ Wco, float* __restrict__ out) {
    extern __shared__ __align__(16) char sm[];
    ull*   ws  = (ull*)(sm + SM_WS_OFF);
    ull*   bs  = (ull*)(sm + SM_BS_OFF);
    float* gsm = (float*)(sm + SM_GSM_OFF);   // [ch][px]
    float* psm = (float*)(sm + SM_PSM_OFF);   // [arr][c][px]
    float* hsm = (float*)(sm + SM_HSM_OFF);   // [ci][10][12]

    const int tid  = threadIdx.x;
    const int tile = blockIdx.x;            // 0..63
    const int b    = blockIdx.y;            // 0..3
    const int th   = (tile >> 3) * 8;
    const int tw   = (tile & 7) * 8;

    // conv role
    const int px    = tid & 63;
    const int slice = tid >> 6;             // 0..3
    const int py    = px >> 3;
    const int pxx   = px & 7;
    const int p0    = slice * 32;

    // recur role: same px, couts [cbase, cbase+16)
    const int cbase = slice * 16;
    const int hw    = (th + py) * W_ + (tw + pxx);

    // ---- prologue: stage weights, bias, peephole params ----
    {
        const ulonglong2* src = (const ulonglong2*)g_Wpk;
        ulonglong2* dst = (ulonglong2*)ws;
#pragma unroll
        for (int i = tid; i < SM_WS_ULL / 2; i += 256)
            dst[i] = src[i];
        if (tid < 128) bs[tid] = g_Bpk[tid];
        for (int i = tid; i < 3 * 4096; i += 256) {
            int arr = i >> 12;
            int c   = (i >> 6) & 63;
            int pl  = i & 63;
            int hh  = th + (pl >> 3);
            int ww  = tw + (pl & 7);
            const float* s = (arr == 0) ? Wci : (arr == 1) ? Wcf : Wco;
            psm[i] = s[c * HW_ + hh * W_ + ww];
        }
    }

    // xd: duplicated input taps {x,x}; layout [ci][kd][kh*3+kw]
    ull xd[KTAPS];
#pragma unroll
    for (int k = 0; k < KTAPS; k++) xd[k] = 0ull;   // causal time pad (t=-1)

    float Cst[16];
#pragma unroll
    for (int j = 0; j < 16; j++) Cst[j] = 0.f;

    const ulonglong2* ws2 = (const ulonglong2*)ws;
    const size_t obase0 = ((size_t)b * COUT_) * T_ * HW_;

    for (int t = 0; t < T_; t++) {
        // ---- stage halo plane for time t (3 ci x 10 x 10, 12-pad cols) ----
        for (int i = tid; i < 300; i += 256) {
            int ci = i / 100;
            int rr = (i - ci * 100) / 10;
            int cc = i - ci * 100 - rr * 10;
            int hh = th - 1 + rr;
            int ww = tw - 1 + cc;
            float v = 0.f;
            if (hh >= 0 && hh < H_ && ww >= 0 && ww < W_)
                v = X[(((size_t)b * CIN_ + ci) * T_ + t) * HW_ + hh * W_ + ww];
            hsm[ci * 120 + rr * 12 + cc] = v;
        }
        __syncthreads();

        // ---- rotate time planes in regs, load new kd=1 plane ----
#pragma unroll
        for (int ci = 0; ci < 3; ci++) {
#pragma unroll
            for (int j = 0; j < 9; j++) {
                xd[ci * 18 + j] = xd[ci * 18 + 9 + j];
                float v = hsm[ci * 120 + (py + j / 3) * 12 + (pxx + j % 3)];
                xd[ci * 18 + 9 + j] = pack2(v, v);
            }
        }

        // ---- conv: 32 channel-pairs, 54 taps each, 4-acc rotation ----
        for (int p = p0; p < p0 + 32; p++) {
            ull a0 = bs[p];
            ull a1 = 0ull, a2 = 0ull, a3 = 0ull;
            const ulonglong2* wr = ws2 + p * 27;
#pragma unroll
            for (int kk = 0; kk < 27; kk++) {
                ulonglong2 w2 = wr[kk];
                if ((kk & 1) == 0) {
                    a0 = fma2(xd[2 * kk],     w2.x, a0);
                    a1 = fma2(xd[2 * kk + 1], w2.y, a1);
                } else {
                    a2 = fma2(xd[2 * kk],     w2.x, a2);
                    a3 = fma2(xd[2 * kk + 1], w2.y, a3);
                }
            }
            float slo, shi;
            unpack2(add2(add2(a0, a1), add2(a2, a3)), slo, shi);
            gsm[(2 * p) * 64 + px]     = slo;
            gsm[(2 * p + 1) * 64 + px] = shi;
        }
        __syncthreads();

        // ---- recurrence step: 16 (px, cout) items per thread ----
        const size_t tof = (size_t)t * HW_ + hw;
#pragma unroll
        for (int j = 0; j < 16; j++) {
            int c = cbase + j;
            float iv = gsm[c * 64 + px];
            float fv = gsm[(64 + c) * 64 + px];
            float gv = gsm[(128 + c) * 64 + px];
            float ov = gsm[(192 + c) * 64 + px];
            float wci = psm[c * 64 + px];
            float wcf = psm[4096 + c * 64 + px];
            float wco = psm[8192 + c * 64 + px];

            float C  = Cst[j];
            float ig = sig_fast(iv + wci * C);
            float fg = sig_fast(fv + wcf * C);
            float Cn = fg * C + ig * tanh_fast(gv);
            float og = sig_fast(ov + wco * Cn);
            out[obase0 + (size_t)c * (T_ * HW_) + tof] = og * tanh_fast(Cn);
            Cst[j] = Cn;
        }
        __syncthreads();
    }
}

// ---------------------------------------------------------------------------
// kernel_launch
// ---------------------------------------------------------------------------
extern "C" void kernel_launch(void* const* d_in, const int* in_sizes, int n_in,
                              void* d_out, int out_size) {
    const float* X     = (const float*)d_in[0];
    const float* Wc    = (const float*)d_in[1];
    const float* bconv = (const float*)d_in[2];
    const float* Wci   = (const float*)d_in[3];
    const float* Wcf   = (const float*)d_in[4];
    const float* Wco   = (const float*)d_in[5];
    float* out = (float*)d_out;

    cudaFuncSetAttribute(fused_kernel, cudaFuncAttributeMaxDynamicSharedMemorySize,
                         SM_TOTAL);

    pack_kernel<<<27, 256>>>(Wc, bconv);

    dim3 grid(64, B_);   // 64 tiles x 4 batches = 256 CTAs
    fused_kernel<<<grid, 256, SM_TOTAL>>>(X, Wci, Wcf, Wco, out);
}

// round 4
// speedup vs baseline: 1.1259x; 1.1259x over previous
#include <cuda_runtime.h>
#include <cstdint>
#include <cstddef>

typedef unsigned long long ull;

// ---------------------------------------------------------------------------
// f32x2 packed-math + fast activation helpers (sm_103a)
// ---------------------------------------------------------------------------
__device__ __forceinline__ ull pack2(float lo, float hi) {
    ull r;
    asm("mov.b64 %0, {%1, %2};" : "=l"(r) : "f"(lo), "f"(hi));
    return r;
}
__device__ __forceinline__ void unpack2(ull v, float& lo, float& hi) {
    asm("mov.b64 {%0, %1}, %2;" : "=f"(lo), "=f"(hi) : "l"(v));
}
__device__ __forceinline__ ull fma2(ull a, ull b, ull c) {
    ull d;
    asm("fma.rn.f32x2 %0, %1, %2, %3;" : "=l"(d) : "l"(a), "l"(b), "l"(c));
    return d;
}
__device__ __forceinline__ float tanh_fast(float x) {
    float y;
    asm("tanh.approx.f32 %0, %1;" : "=f"(y) : "f"(x));
    return y;
}
__device__ __forceinline__ float sig_fast(float x) {
    return fmaf(0.5f, tanh_fast(0.5f * x), 0.5f);
}

// ---------------------------------------------------------------------------
// Problem constants
// ---------------------------------------------------------------------------
#define B_    4
#define CIN_  3
#define T_    32
#define H_    64
#define W_    64
#define COUT_ 64
#define NCH_  256
#define HW_   4096

// Weights packed by time-tap: g_Wpk2[ch][j] = {w(kd=0, pos j), w(kd=1, pos j)}
// where j = ci*9 + kh*3 + kw (27 positions, padded to 28 with zeros).
__device__ ull g_Wpk2[NCH_ * 28];
__device__ ull g_Bpk2[NCH_];           // {bias, 0}

__global__ void __launch_bounds__(256)
pack_kernel(const float* __restrict__ Wc, const float* __restrict__ bconv) {
    int i = blockIdx.x * 256 + threadIdx.x;
    if (i < NCH_ * 28) {
        int o = i / 28;
        int j = i - o * 28;
        ull v = 0ull;
        if (j < 27) {
            int ci  = j / 9;
            int khw = j - ci * 9;
            // Wc layout (O, I, D, kH, kW): o*54 + ci*18 + kd*9 + khw
            v = pack2(Wc[o * 54 + ci * 18 + khw],
                      Wc[o * 54 + ci * 18 + 9 + khw]);
        }
        g_Wpk2[i] = v;
    }
    if (i < NCH_) g_Bpk2[i] = pack2(bconv[i], 0.f);
}

// ---------------------------------------------------------------------------
// Fused conv + QRNN, register-resident gates.
// CTA = 8x8 pixel tile; 512 threads = 64 px x 8 cout-slices (8 couts each).
// Each thread computes, per t, the 4 gate channels of each of its 8 couts
// (accumulated in registers, tap-packed over kd) and runs the LSTM step
// immediately — no gate staging in shared.
// ---------------------------------------------------------------------------
#define CT_ 512
#define SM_WS_OFF   0
#define SM_WS_BYTES (NCH_ * 14 * 16)               // 57344: [ch][14] ulonglong2
#define SM_BS_OFF   SM_WS_BYTES                    // 57344: 256 ull bias pairs
#define SM_PSM_OFF  (SM_BS_OFF + NCH_ * 8)         // 59392: [3][64][64px] f32
#define SM_HSM_OFF  (SM_PSM_OFF + 3 * 64 * 64 * 4) // 108544: halo 2x[3][10][12]
#define SM_TOTAL    (SM_HSM_OFF + 2 * 360 * 4)     // 111424 B

__global__ void __launch_bounds__(CT_, 1)
fused_kernel(const float* __restrict__ X,
             const float* __restrict__ Wci, const float* __restrict__ Wcf,
             const float* __restrict__ Wco, float* __restrict__ out) {
    extern __shared__ __align__(16) char sm[];
    const ulonglong2* ws2 = (const ulonglong2*)(sm + SM_WS_OFF);
    const ull* bsm = (const ull*)(sm + SM_BS_OFF);
    float* psm = (float*)(sm + SM_PSM_OFF);
    float* hsm = (float*)(sm + SM_HSM_OFF);   // [buf][ci][10][12]

    const int tid   = threadIdx.x;
    const int tile  = blockIdx.x;              // 0..63
    const int bgrp  = blockIdx.y;              // 0..1
    const int th    = (tile >> 3) * 8;
    const int tw    = (tile & 7) * 8;
    const int px    = tid & 63;
    const int slice = tid >> 6;                // 0..7
    const int cbase = slice * 8;               // 8 couts per thread
    const int py    = px >> 3;
    const int pxx   = px & 7;
    const int hw    = (th + py) * W_ + (tw + pxx);

    // ---- prologue: stage packed weights + bias + peephole params ----
    {
        const ulonglong2* src = (const ulonglong2*)g_Wpk2;
        ulonglong2* dst = (ulonglong2*)(sm + SM_WS_OFF);
#pragma unroll
        for (int i = tid; i < NCH_ * 14; i += CT_)
            dst[i] = src[i];
        if (tid < NCH_) ((ull*)(sm + SM_BS_OFF))[tid] = g_Bpk2[tid];
        for (int i = tid; i < 3 * 4096; i += CT_) {
            int arr = i >> 12;
            int c   = (i >> 6) & 63;
            int pl  = i & 63;
            int hh  = th + (pl >> 3);
            int ww  = tw + (pl & 7);
            const float* s = (arr == 0) ? Wci : (arr == 1) ? Wcf : Wco;
            psm[i] = s[c * HW_ + hh * W_ + ww];
        }
    }

    // Halo staging assignment (threads 0..299 each own one element)
    int hs_idx = -1, hs_off = 0;
    bool hs_ok = false;
    if (tid < 300) {
        int ci = tid / 100;
        int rr = (tid - ci * 100) / 10;
        int cc = tid - ci * 100 - rr * 10;
        int hh = th - 1 + rr;
        int ww = tw - 1 + cc;
        hs_ok  = (hh >= 0 && hh < H_ && ww >= 0 && ww < W_);
        hs_idx = ci * 120 + rr * 12 + cc;
        hs_off = ci * (T_ * HW_) + hh * W_ + ww;   // within (ci, t, h, w), t added later
    }

    for (int bi = 0; bi < 2; bi++) {
        const int b = bgrp * 2 + bi;
        const float* Xb = X + (size_t)b * CIN_ * T_ * HW_;
        const size_t obase = ((size_t)b * COUT_) * T_ * HW_ + hw;

        // xd[j] = {x(t-1, pos j), x(t, pos j)}, j = ci*9+kh*3+kw; xd[27] = 0 pad
        ull xd[28];
#pragma unroll
        for (int k = 0; k < 28; k++) xd[k] = 0ull;
        float Cst[8];
#pragma unroll
        for (int k = 0; k < 8; k++) Cst[k] = 0.f;

        for (int t = 0; t < T_; t++) {
            float* hbuf = hsm + (t & 1) * 360;
            // ---- stage halo plane for time t ----
            if (tid < 300)
                hbuf[hs_idx] = hs_ok ? Xb[hs_off + (size_t)t * HW_] : 0.f;
            __syncthreads();

            // ---- rotate xd: lo <- hi, hi <- x(t) ----
#pragma unroll
            for (int j = 0; j < 27; j++) {
                int ci = j / 9;
                int r  = (j - ci * 9) / 3;
                int cc = j - ci * 9 - r * 3;
                float lo, hi;
                unpack2(xd[j], lo, hi);
                float nv = hbuf[ci * 120 + (py + r) * 12 + (pxx + cc)];
                xd[j] = pack2(hi, nv);
            }

            // ---- per cout: 4 gate channels via tap-packed fma2, then LSTM ----
            const size_t tof = (size_t)t * HW_;
#pragma unroll
            for (int k = 0; k < 8; k++) {
                const int c = cbase + k;
                ull a0 = bsm[c];
                ull a1 = bsm[c + 64];
                ull a2 = bsm[c + 128];
                ull a3 = bsm[c + 192];
                const ulonglong2* w0 = ws2 + (size_t)c * 14;
                const ulonglong2* w1 = w0 + 64 * 14;
                const ulonglong2* w2 = w0 + 128 * 14;
                const ulonglong2* w3 = w0 + 192 * 14;
#pragma unroll
                for (int jj = 0; jj < 14; jj++) {
                    ulonglong2 W0 = w0[jj], W1 = w1[jj], W2 = w2[jj], W3 = w3[jj];
                    ull xa = xd[2 * jj], xb = xd[2 * jj + 1];
                    a0 = fma2(xa, W0.x, a0);
                    a1 = fma2(xa, W1.x, a1);
                    a2 = fma2(xa, W2.x, a2);
                    a3 = fma2(xa, W3.x, a3);
                    a0 = fma2(xb, W0.y, a0);
                    a1 = fma2(xb, W1.y, a1);
                    a2 = fma2(xb, W2.y, a2);
                    a3 = fma2(xb, W3.y, a3);
                }
                float l0, h0, l1, h1, l2, h2, l3, h3;
                unpack2(a0, l0, h0);
                unpack2(a1, l1, h1);
                unpack2(a2, l2, h2);
                unpack2(a3, l3, h3);
                float iv = l0 + h0;
                float fv = l1 + h1;
                float gv = l2 + h2;
                float ov = l3 + h3;

                float wci = psm[c * 64 + px];
                float wcf = psm[4096 + c * 64 + px];
                float wco = psm[8192 + c * 64 + px];

                float C  = Cst[k];
                float ig = sig_fast(iv + wci * C);
                float fg = sig_fast(fv + wcf * C);
                float Cn = fg * C + ig * tanh_fast(gv);
                float og = sig_fast(ov + wco * Cn);
                out[obase + (size_t)c * (T_ * HW_) + tof] = og * tanh_fast(Cn);
                Cst[k] = Cn;
            }
            __syncthreads();
        }
    }
}

// ---------------------------------------------------------------------------
// kernel_launch
// ---------------------------------------------------------------------------
extern "C" void kernel_launch(void* const* d_in, const int* in_sizes, int n_in,
                              void* d_out, int out_size) {
    const float* X     = (const float*)d_in[0];
    const float* Wc    = (const float*)d_in[1];
    const float* bconv = (const float*)d_in[2];
    const float* Wci   = (const float*)d_in[3];
    const float* Wcf   = (const float*)d_in[4];
    const float* Wco   = (const float*)d_in[5];
    float* out = (float*)d_out;

    cudaFuncSetAttribute(fused_kernel, cudaFuncAttributeMaxDynamicSharedMemorySize,
                         SM_TOTAL);

    pack_kernel<<<29, 256>>>(Wc, bconv);

    dim3 grid(64, 2);   // 64 tiles x 2 batch-groups = 128 CTAs (1 wave)
    fused_kernel<<<grid, CT_, SM_TOTAL>>>(X, Wci, Wcf, Wco, out);
}

// round 6
// speedup vs baseline: 2.8714x; 2.5504x over previous
#include <cuda_runtime.h>
#include <cstdint>
#include <cstddef>

// ---------------------------------------------------------------------------
// Portable PTX helpers (no sm_103a-suffix instructions!)
// ---------------------------------------------------------------------------
__device__ __forceinline__ uint32_t smem_u32(const void* p) {
    uint32_t a;
    asm("{ .reg .u64 t; cvta.to.shared.u64 t, %1; cvt.u32.u64 %0, t; }"
        : "=r"(a) : "l"(p));
    return a;
}
__device__ __forceinline__ float tanh_fast(float x) {
    float y;
    asm("tanh.approx.f32 %0, %1;" : "=f"(y) : "f"(x));
    return y;
}
__device__ __forceinline__ float sig_fast(float x) {
    return fmaf(0.5f, tanh_fast(0.5f * x), 0.5f);
}
// pack two f32 -> f16x2 {lo, hi}
__device__ __forceinline__ uint32_t f16x2(float hi, float lo) {
    uint32_t r;
    asm("cvt.rn.f16x2.f32 %0, %1, %2;" : "=r"(r) : "f"(hi), "f"(lo));
    return r;
}
__device__ __forceinline__ void ldmatrix_x4(uint32_t& r0, uint32_t& r1,
                                            uint32_t& r2, uint32_t& r3,
                                            uint32_t addr) {
    asm volatile("ldmatrix.sync.aligned.m8n8.x4.shared.b16 {%0,%1,%2,%3}, [%4];"
                 : "=r"(r0), "=r"(r1), "=r"(r2), "=r"(r3) : "r"(addr));
}
__device__ __forceinline__ void mma16816(float* d, uint32_t a0, uint32_t a1,
                                         uint32_t a2, uint32_t a3,
                                         uint32_t b0, uint32_t b1) {
    asm volatile(
        "mma.sync.aligned.m16n8k16.row.col.f32.f16.f16.f32 "
        "{%0,%1,%2,%3}, {%4,%5,%6,%7}, {%8,%9}, {%0,%1,%2,%3};"
        : "+f"(d[0]), "+f"(d[1]), "+f"(d[2]), "+f"(d[3])
        : "r"(a0), "r"(a1), "r"(a2), "r"(a3), "r"(b0), "r"(b1));
}
__device__ __forceinline__ uint32_t sw128(uint32_t off) {
    return off ^ ((off >> 3) & 0x70);
}

// ---------------------------------------------------------------------------
// Problem constants
// ---------------------------------------------------------------------------
#define B_    4
#define T_    32
#define H_    64
#define W_    64
#define COUT_ 64
#define HW_   4096

// SMEM layout (bytes)
#define SM_B_OFF    0                    // B fp16 [256 n][128 B]     = 32768
#define SM_A_OFF    32768                // A fp16 [128 px][128 B]    = 16384
#define SM_PSM_OFF  49152                // peephole [3][64][128] f32 = 98304
#define SM_HALO_OFF 147456               // halo 2 x [3][18][10] f32  = 4320
#define SM_TOTAL    151776

__global__ void __launch_bounds__(256, 1)
fused_mma_kernel(const float* __restrict__ X,
                 const float* __restrict__ Wc, const float* __restrict__ bconv,
                 const float* __restrict__ Wci, const float* __restrict__ Wcf,
                 const float* __restrict__ Wco, float* __restrict__ out) {
    extern __shared__ __align__(1024) char sm[];
    const uint32_t smb = smem_u32(sm);
    float* psm = (float*)(sm + SM_PSM_OFF);
    float* hsm = (float*)(sm + SM_HALO_OFF);    // [buf][ci*180 + rr*10 + cc]

    const int tid  = threadIdx.x;
    const int wid  = tid >> 5;                  // 0..7 : M-tile
    const int lane = tid & 31;
    const int tile = blockIdx.x;                // 0..31
    const int b    = blockIdx.y;                // 0..3
    const int trow = (tile >> 3) * 16;
    const int tcol = (tile & 7) * 8;

    // ---- prologue: B (weights+bias fp16, SW128), A const cols, psm ----
    // B row n = cout*4 + gate  <->  conv out-channel o = gate*64 + cout
    for (int i = tid; i < 256 * 32; i += 256) {
        int n = i >> 5;
        int p = i & 31;
        int o = (n & 3) * 64 + (n >> 2);
        float v0 = 0.f, v1 = 0.f;
        if (p < 27) {
            v0 = Wc[o * 54 + 2 * p];
            v1 = Wc[o * 54 + 2 * p + 1];
        } else if (p == 27) {
            v0 = bconv[o];                      // bias rides as K=54
        }
        *(uint32_t*)(sm + SM_B_OFF + sw128((uint32_t)(n * 128 + p * 4))) = f16x2(v1, v0);
    }
    // A const pairs 27..31: pair27 = {1.0, 0} (K=54 ones col), rest 0
    for (int i = tid; i < 128 * 5; i += 256) {
        int px = i / 5;
        int p  = 27 + (i - px * 5);
        uint32_t v = (p == 27) ? f16x2(0.f, 1.f) : 0u;
        *(uint32_t*)(sm + SM_A_OFF + sw128((uint32_t)(px * 128 + p * 4))) = v;
    }
    // peephole params: psm[arr][c][px]
    for (int i = tid; i < 3 * 64 * 128; i += 256) {
        int arr = i >> 13;
        int rem = i & 8191;
        int c   = rem >> 7;
        int pl  = rem & 127;
        int hh  = trow + (pl >> 3);
        int ww  = tcol + (pl & 7);
        const float* s = (arr == 0) ? Wci : (arr == 1) ? Wcf : Wco;
        psm[i] = s[c * HW_ + hh * W_ + ww];
    }
    // zero halo buffer for t = -1 (slot 1)
    for (int i = tid; i < 540; i += 256) hsm[540 + i] = 0.f;
    __syncthreads();

    // ---- lane-constant ldmatrix addresses ----
    const int g  = lane >> 3;                   // matrix group 0..3
    const int r8 = lane & 7;
    const uint32_t cL = (uint32_t)r8 << 4;      // SW128 XOR for this lane's row
    // A: m0 rows px0+r klo | m1 rows px0+8+r klo | m2 px0+r khi | m3 px0+8+r khi
    const int rowA = wid * 16 + r8 + 8 * (g & 1);
    const uint32_t dkA = (uint32_t)(g >> 1) * 16;
    const uint32_t aBase = smb + SM_A_OFF + (uint32_t)rowA * 128;
    // B: m0 rows n0+r klo | m1 rows n0+r khi | m2 n0+8+r klo | m3 n0+8+r khi
    const int rowB = r8 + 8 * (g >> 1);
    const uint32_t dkB = (uint32_t)(g & 1) * 16;
    const uint32_t bBase = smb + SM_B_OFF + (uint32_t)rowB * 128;

    // ---- recurrence roles ----
    const int q   = lane & 3;
    const int b1g = q & 1;                      // 0: holds (i,f); 1: holds (g,o)
    const int cq  = (q >> 1) & 1;               // cout parity within n-tile
    const int px_t = wid * 16 + (lane >> 2) + 8 * b1g;
    const int hw   = (trow + (px_t >> 3)) * W_ + tcol + (px_t & 7);

    const float* pp = psm + cq * 128 + px_t;    // + nt*256 per n-tile
    float* outp = out + (size_t)b * COUT_ * T_ * HW_ + (size_t)cq * (T_ * HW_) + hw;

    float C[32];
#pragma unroll
    for (int m = 0; m < 32; m++) C[m] = 0.f;

    const float* Xb = X + (size_t)b * 3 * T_ * HW_;

    for (int t = 0; t < T_; t++) {
        // ---- stage halo(t) into slot t&1 ----
        float* hb = hsm + (t & 1) * 540;
        for (int i = tid; i < 540; i += 256) {
            int ci = i / 180;
            int rem = i - ci * 180;
            int rr = rem / 10;
            int cc = rem - rr * 10;
            int hh = trow - 1 + rr;
            int ww = tcol - 1 + cc;
            float v = 0.f;
            if (hh >= 0 && hh < H_ && ww >= 0 && ww < W_)
                v = Xb[((size_t)ci * T_ + t) * HW_ + hh * W_ + ww];
            hb[i] = v;
        }
        __syncthreads();

        // ---- build A(t) pairs 0..26: k = ci*18 + kd*9 + kh*3 + kw ----
        for (int i = tid; i < 128 * 27; i += 256) {
            int px = i / 27;
            int p  = i - px * 27;
            int rr = px >> 3;
            int cc = px & 7;
            float v[2];
#pragma unroll
            for (int u = 0; u < 2; u++) {
                int k  = 2 * p + u;
                int ci = k / 18;
                int r2 = k - ci * 18;
                int kd = (r2 >= 9) ? 1 : 0;
                int j  = r2 - kd * 9;
                int kh = j / 3;
                int kw = j - kh * 3;
                const float* buf = hsm + (((t + 1 + kd) & 1) * 540);
                v[u] = buf[ci * 180 + (rr + kh) * 10 + (cc + kw)];
            }
            *(uint32_t*)(sm + SM_A_OFF + sw128((uint32_t)(px * 128 + p * 4))) = f16x2(v[1], v[0]);
        }
        __syncthreads();

        // ---- MMA: D[16px x 256ch] per warp, K=64 in 4 chunks ----
        float acc[128];
#pragma unroll
        for (int m = 0; m < 128; m++) acc[m] = 0.f;

#pragma unroll
        for (int kc = 0; kc < 4; kc++) {
            uint32_t a0, a1, a2, a3;
            ldmatrix_x4(a0, a1, a2, a3, aBase + (((uint32_t)kc * 32 + dkA) ^ cL));
#pragma unroll
            for (int np = 0; np < 16; np++) {
                uint32_t b0, b1, b2, b3;
                ldmatrix_x4(b0, b1, b2, b3,
                            bBase + (uint32_t)np * 2048 + (((uint32_t)kc * 32 + dkB) ^ cL));
                mma16816(acc + np * 8,     a0, a1, a2, a3, b0, b1);
                mma16816(acc + np * 8 + 4, a0, a1, a2, a3, b2, b3);
            }
        }

        // ---- recurrence on fragments: one (px,cout) per thread per n-tile ----
        float* outt = outp + (size_t)t * HW_;
#pragma unroll
        for (int nt = 0; nt < 32; nt++) {
            float d0 = acc[nt * 4], d1 = acc[nt * 4 + 1];
            float d2 = acc[nt * 4 + 2], d3 = acc[nt * 4 + 3];
            // exchange within lane pair: even lanes (i,f rows r) <-> odd (g,o rows r+8)
            float t0 = b1g ? d0 : d2;
            float t1 = b1g ? d1 : d3;
            float e0 = __shfl_xor_sync(0xFFFFFFFFu, t0, 1);
            float e1 = __shfl_xor_sync(0xFFFFFFFFu, t1, 1);
            float iv = b1g ? e0 : d0;
            float fv = b1g ? e1 : d1;
            float gv = b1g ? d2 : e0;
            float ov = b1g ? d3 : e1;

            float wci = pp[nt * 256];
            float wcf = pp[8192 + nt * 256];
            float wco = pp[16384 + nt * 256];

            float Cp = C[nt];
            float ig = sig_fast(iv + wci * Cp);
            float fg = sig_fast(fv + wcf * Cp);
            float Cn = fg * Cp + ig * tanh_fast(gv);
            float og = sig_fast(ov + wco * Cn);
            outt[(size_t)nt * (2 * T_ * HW_)] = og * tanh_fast(Cn);
            C[nt] = Cn;
        }
        // next iteration's halo write targets the other slot; the barrier after
        // that write also fences this iteration's ldmatrix reads of A.
    }
}

// ---------------------------------------------------------------------------
// kernel_launch
// ---------------------------------------------------------------------------
extern "C" void kernel_launch(void* const* d_in, const int* in_sizes, int n_in,
                              void* d_out, int out_size) {
    const float* X     = (const float*)d_in[0];
    const float* Wc    = (const float*)d_in[1];
    const float* bconv = (const float*)d_in[2];
    const float* Wci   = (const float*)d_in[3];
    const float* Wcf   = (const float*)d_in[4];
    const float* Wco   = (const float*)d_in[5];
    float* out = (float*)d_out;

    cudaFuncSetAttribute(fused_mma_kernel, cudaFuncAttributeMaxDynamicSharedMemorySize,
                         SM_TOTAL);

    dim3 grid(32, B_);   // 32 tiles x 4 batches = 128 CTAs (one wave)
    fused_mma_kernel<<<grid, 256, SM_TOTAL>>>(X, Wc, bconv, Wci, Wcf, Wco, out);
}

// round 7
// speedup vs baseline: 3.3525x; 1.1676x over previous
#include <cuda_runtime.h>
#include <cstdint>
#include <cstddef>

// ---------------------------------------------------------------------------
// Portable PTX helpers (base sm_103 target: no 'a'-suffix instructions)
// ---------------------------------------------------------------------------
__device__ __forceinline__ uint32_t smem_u32(const void* p) {
    uint32_t a;
    asm("{ .reg .u64 t; cvta.to.shared.u64 t, %1; cvt.u32.u64 %0, t; }"
        : "=r"(a) : "l"(p));
    return a;
}
__device__ __forceinline__ float tanh_fast(float x) {
    float y;
    asm("tanh.approx.f32 %0, %1;" : "=f"(y) : "f"(x));
    return y;
}
__device__ __forceinline__ float sig_fast(float x) {
    return fmaf(0.5f, tanh_fast(0.5f * x), 0.5f);
}
// pack two f32 -> f16x2 {lo, hi}
__device__ __forceinline__ uint32_t f16x2(float hi, float lo) {
    uint32_t r;
    asm("cvt.rn.f16x2.f32 %0, %1, %2;" : "=r"(r) : "f"(hi), "f"(lo));
    return r;
}
__device__ __forceinline__ void ldmatrix_x4(uint32_t& r0, uint32_t& r1,
                                            uint32_t& r2, uint32_t& r3,
                                            uint32_t addr) {
    asm volatile("ldmatrix.sync.aligned.m8n8.x4.shared.b16 {%0,%1,%2,%3}, [%4];"
                 : "=r"(r0), "=r"(r1), "=r"(r2), "=r"(r3) : "r"(addr));
}
__device__ __forceinline__ void mma16816(float* d, uint32_t a0, uint32_t a1,
                                         uint32_t a2, uint32_t a3,
                                         uint32_t b0, uint32_t b1) {
    asm volatile(
        "mma.sync.aligned.m16n8k16.row.col.f32.f16.f16.f32 "
        "{%0,%1,%2,%3}, {%4,%5,%6,%7}, {%8,%9}, {%0,%1,%2,%3};"
        : "+f"(d[0]), "+f"(d[1]), "+f"(d[2]), "+f"(d[3])
        : "r"(a0), "r"(a1), "r"(a2), "r"(a3), "r"(b0), "r"(b1));
}
__device__ __forceinline__ uint32_t sw128(uint32_t off) {
    return off ^ ((off >> 3) & 0x70);
}

// ---------------------------------------------------------------------------
// Problem constants
// ---------------------------------------------------------------------------
#define B_    4
#define T_    32
#define H_    64
#define W_    64
#define COUT_ 64
#define HW_   4096

// K layout: k = j*2 + kd, j = ci*9 + kh*3 + kw (j=0..26); pair p = j, halves = kd.
// Pair 27: A = {1.0, 0}, B = {bias, 0}. Pairs 28..31 zero.
// B row n: tile8 = n>>3, u_g = tile8>>1, gsel = tile8&1, jj = n&7,
//          cout c = u_g*4 + (jj>>1), gate = gsel*2 + (jj&1), o = gate*64 + c.

// SMEM layout (bytes)
#define SM_B_OFF    0                    // B fp16 [256 n][128 B]     = 32768
#define SM_A_OFF    32768                // A fp16 [128 px][128 B]    = 16384
#define SM_PSM_OFF  49152                // peephole [3][64][128] f32 = 98304
#define SM_HALO_OFF 147456               // halo 2 x [3][18][10] f32  = 4320
#define SM_TOTAL    151776

#define CT_ 512

__global__ void __launch_bounds__(CT_, 1)
fused_mma_kernel(const float* __restrict__ X,
                 const float* __restrict__ Wc, const float* __restrict__ bconv,
                 const float* __restrict__ Wci, const float* __restrict__ Wcf,
                 const float* __restrict__ Wco, float* __restrict__ out) {
    extern __shared__ __align__(1024) char sm[];
    const uint32_t smb = smem_u32(sm);
    float* psm = (float*)(sm + SM_PSM_OFF);
    float* hsm = (float*)(sm + SM_HALO_OFF);    // [buf][ci*180 + rr*10 + cc]

    const int tid  = threadIdx.x;
    const int wid  = tid >> 5;                  // 16 warps
    const int lane = tid & 31;
    const int mt   = wid & 7;                   // M-tile 0..7
    const int nh   = wid >> 3;                  // N-half 0..1
    const int tile = blockIdx.x;                // 0..31
    const int b    = blockIdx.y;                // 0..3
    const int trow = (tile >> 3) * 16;
    const int tcol = (tile & 7) * 8;

    // ---- prologue ----
    for (int i = tid; i < 256 * 32; i += CT_) {
        int n = i >> 5;
        int p = i & 31;
        int tile8 = n >> 3;
        int jj    = n & 7;
        int c     = (tile8 >> 1) * 4 + (jj >> 1);
        int gate  = (tile8 & 1) * 2 + (jj & 1);
        int o     = gate * 64 + c;
        float v0 = 0.f, v1 = 0.f;
        if (p < 27) {
            int ci  = p / 9;
            int khw = p - ci * 9;
            v0 = Wc[o * 54 + ci * 18 + khw];        // kd = 0
            v1 = Wc[o * 54 + ci * 18 + 9 + khw];    // kd = 1
        } else if (p == 27) {
            v0 = bconv[o];
        }
        *(uint32_t*)(sm + SM_B_OFF + sw128((uint32_t)(n * 128 + p * 4))) = f16x2(v1, v0);
    }
    // A const pairs 27..31
    for (int i = tid; i < 128 * 5; i += CT_) {
        int px = i / 5;
        int p  = 27 + (i - px * 5);
        uint32_t v = (p == 27) ? f16x2(0.f, 1.f) : 0u;
        *(uint32_t*)(sm + SM_A_OFF + sw128((uint32_t)(px * 128 + p * 4))) = v;
    }
    // peephole params: psm[arr][c][px]
    for (int i = tid; i < 3 * 64 * 128; i += CT_) {
        int arr = i >> 13;
        int rem = i & 8191;
        int c   = rem >> 7;
        int pl  = rem & 127;
        int hh  = trow + (pl >> 3);
        int ww  = tcol + (pl & 7);
        const float* s = (arr == 0) ? Wci : (arr == 1) ? Wcf : Wco;
        psm[i] = s[c * HW_ + hh * W_ + ww];
    }
    // zero halo slot 1 (t = -1 plane)
    for (int i = tid; i < 540; i += CT_) hsm[540 + i] = 0.f;
    __syncthreads();

    // ---- lane-constant ldmatrix addresses ----
    const int g  = lane >> 3;
    const int r8 = lane & 7;
    const uint32_t cL = (uint32_t)r8 << 4;
    const int rowA = mt * 16 + r8 + 8 * (g & 1);
    const uint32_t dkA = (uint32_t)(g >> 1) * 16;
    const uint32_t aBase = smb + SM_A_OFF + (uint32_t)rowA * 128;
    const int rowB = r8 + 8 * (g >> 1);
    const uint32_t dkB = (uint32_t)(g & 1) * 16;
    const uint32_t bBase = smb + SM_B_OFF + (uint32_t)nh * 16384 + (uint32_t)rowB * 128;

    // ---- recurrence roles: rows px0, px0+8; couts cbase + 4v ----
    const int q    = lane & 3;
    const int px0  = mt * 16 + (lane >> 2);
    const int px1  = px0 + 8;
    const int hw0  = (trow + (px0 >> 3)) * W_ + tcol + (px0 & 7);
    const int hw1  = (trow + (px1 >> 3)) * W_ + tcol + (px1 & 7);
    const int cb   = nh * 32 + q;               // cout for v=0; +4 per v

    const float* pci0 = psm + cb * 128 + px0;
    const float* pci1 = psm + cb * 128 + px1;
    float* outp0 = out + ((size_t)b * COUT_ + cb) * (T_ * HW_) + hw0;
    float* outp1 = out + ((size_t)b * COUT_ + cb) * (T_ * HW_) + hw1;

    float C[16];
#pragma unroll
    for (int m = 0; m < 16; m++) C[m] = 0.f;

    const float* Xb = X + (size_t)b * 3 * T_ * HW_;

    for (int t = 0; t < T_; t++) {
        // ---- stage halo(t) into slot t&1 ----
        float* hb = hsm + (t & 1) * 540;
        for (int i = tid; i < 540; i += CT_) {
            int ci = i / 180;
            int rem = i - ci * 180;
            int rr = rem / 10;
            int cc = rem - rr * 10;
            int hh = trow - 1 + rr;
            int ww = tcol - 1 + cc;
            float v = 0.f;
            if (hh >= 0 && hh < H_ && ww >= 0 && ww < W_)
                v = Xb[((size_t)ci * T_ + t) * HW_ + hh * W_ + ww];
            hb[i] = v;
        }
        __syncthreads();

        // ---- build A(t): pair p = j (one spatial decomp, two time planes) ----
        const int buf0 = ((t & 1) ^ 1) * 540;   // kd = 0 -> x(t-1)
        const int buf1 = (t & 1) * 540;         // kd = 1 -> x(t)
        for (int i = tid; i < 128 * 27; i += CT_) {
            int px = i / 27;
            int p  = i - px * 27;
            int ci  = p / 9;
            int khw = p - ci * 9;
            int kh  = khw / 3;
            int kw  = khw - kh * 3;
            int soff = ci * 180 + ((px >> 3) + kh) * 10 + ((px & 7) + kw);
            float v0 = hsm[buf0 + soff];
            float v1 = hsm[buf1 + soff];
            *(uint32_t*)(sm + SM_A_OFF + sw128((uint32_t)(px * 128 + p * 4))) = f16x2(v1, v0);
        }
        __syncthreads();

        // ---- MMA: per warp D[16 px x 128 ch], K = 64 in 4 chunks ----
        float acc[64];
#pragma unroll
        for (int m = 0; m < 64; m++) acc[m] = 0.f;

#pragma unroll
        for (int kc = 0; kc < 4; kc++) {
            uint32_t a0, a1, a2, a3;
            ldmatrix_x4(a0, a1, a2, a3, aBase + (((uint32_t)kc * 32 + dkA) ^ cL));
#pragma unroll
            for (int np = 0; np < 8; np++) {
                uint32_t b0, b1, b2, b3;
                ldmatrix_x4(b0, b1, b2, b3,
                            bBase + (uint32_t)np * 2048 + (((uint32_t)kc * 32 + dkB) ^ cL));
                mma16816(acc + np * 8,     a0, a1, a2, a3, b0, b1);  // (i,f) tile
                mma16816(acc + np * 8 + 4, a0, a1, a2, a3, b2, b3);  // (g,o) tile
            }
        }

        // ---- recurrence: 8 cout-groups x 2 pixel rows, no shuffles ----
        const size_t tof = (size_t)t * HW_;
#pragma unroll
        for (int v = 0; v < 8; v++) {
            const float* A = acc + v * 8;       // [i0 f0 i1 f1 | g0 o0 g1 o1]
            float wci0 = pci0[v * 512],          wci1 = pci1[v * 512];
            float wcf0 = pci0[8192 + v * 512],   wcf1 = pci1[8192 + v * 512];
            float wco0 = pci0[16384 + v * 512],  wco1 = pci1[16384 + v * 512];
            {
                float Cp = C[2 * v];
                float ig = sig_fast(A[0] + wci0 * Cp);
                float fg = sig_fast(A[1] + wcf0 * Cp);
                float Cn = fg * Cp + ig * tanh_fast(A[4]);
                float og = sig_fast(A[5] + wco0 * Cn);
                outp0[(size_t)v * (4 * T_ * HW_) + tof] = og * tanh_fast(Cn);
                C[2 * v] = Cn;
            }
            {
                float Cp = C[2 * v + 1];
                float ig = sig_fast(A[2] + wci1 * Cp);
                float fg = sig_fast(A[3] + wcf1 * Cp);
                float Cn = fg * Cp + ig * tanh_fast(A[6]);
                float og = sig_fast(A[7] + wco1 * Cn);
                outp1[(size_t)v * (4 * T_ * HW_) + tof] = og * tanh_fast(Cn);
                C[2 * v + 1] = Cn;
            }
        }
    }
}

// ---------------------------------------------------------------------------
// kernel_launch
// ---------------------------------------------------------------------------
extern "C" void kernel_launch(void* const* d_in, const int* in_sizes, int n_in,
                              void* d_out, int out_size) {
    const float* X     = (const float*)d_in[0];
    const float* Wc    = (const float*)d_in[1];
    const float* bconv = (const float*)d_in[2];
    const float* Wci   = (const float*)d_in[3];
    const float* Wcf   = (const float*)d_in[4];
    const float* Wco   = (const float*)d_in[5];
    float* out = (float*)d_out;

    cudaFuncSetAttribute(fused_mma_kernel, cudaFuncAttributeMaxDynamicSharedMemorySize,
                         SM_TOTAL);

    dim3 grid(32, B_);   // 32 tiles x 4 batches = 128 CTAs (one wave)
    fused_mma_kernel<<<grid, CT_, SM_TOTAL>>>(X, Wc, bconv, Wci, Wcf, Wco, out);
}

// round 8
// speedup vs baseline: 5.0484x; 1.5058x over previous
#include <cuda_runtime.h>
#include <cstdint>
#include <cstddef>

// ---------------------------------------------------------------------------
// Portable PTX helpers (base sm_103 target: no 'a'-suffix instructions)
// ---------------------------------------------------------------------------
__device__ __forceinline__ uint32_t smem_u32(const void* p) {
    uint32_t a;
    asm("{ .reg .u64 t; cvta.to.shared.u64 t, %1; cvt.u32.u64 %0, t; }"
        : "=r"(a) : "l"(p));
    return a;
}
__device__ __forceinline__ float tanh_fast(float x) {
    float y;
    asm("tanh.approx.f32 %0, %1;" : "=f"(y) : "f"(x));
    return y;
}
__device__ __forceinline__ float sig_fast(float x) {
    return fmaf(0.5f, tanh_fast(0.5f * x), 0.5f);
}
// pack two f32 -> f16x2 {lo, hi}
__device__ __forceinline__ uint32_t f16x2(float hi, float lo) {
    uint32_t r;
    asm("cvt.rn.f16x2.f32 %0, %1, %2;" : "=r"(r) : "f"(hi), "f"(lo));
    return r;
}
__device__ __forceinline__ void ldmatrix_x4(uint32_t& r0, uint32_t& r1,
                                            uint32_t& r2, uint32_t& r3,
                                            uint32_t addr) {
    asm volatile("ldmatrix.sync.aligned.m8n8.x4.shared.b16 {%0,%1,%2,%3}, [%4];"
                 : "=r"(r0), "=r"(r1), "=r"(r2), "=r"(r3) : "r"(addr));
}
__device__ __forceinline__ void mma16816(float* d, uint32_t a0, uint32_t a1,
                                         uint32_t a2, uint32_t a3,
                                         uint32_t b0, uint32_t b1) {
    asm volatile(
        "mma.sync.aligned.m16n8k16.row.col.f32.f16.f16.f32 "
        "{%0,%1,%2,%3}, {%4,%5,%6,%7}, {%8,%9}, {%0,%1,%2,%3};"
        : "+f"(d[0]), "+f"(d[1]), "+f"(d[2]), "+f"(d[3])
        : "r"(a0), "r"(a1), "r"(a2), "r"(a3), "r"(b0), "r"(b1));
}
__device__ __forceinline__ uint32_t sw128(uint32_t off) {
    return off ^ ((off >> 3) & 0x70);
}

// ---------------------------------------------------------------------------
// Problem constants
// ---------------------------------------------------------------------------
#define B_    4
#define T_    32
#define H_    64
#define W_    64
#define COUT_ 64
#define HW_   4096

// K layout: pair p = j = ci*9+kh*3+kw (0..26), halves = kd {t-1, t}.
// Pair 27: A = {1.0, 0}, B = {bias, 0}. Pairs 28..31 zero.
// B row n: tile8=n>>3, jj=n&7 -> cout c=(tile8>>1)*4+(jj>>1), gate=(tile8&1)*2+(jj&1)

#define PSTRIDE 132                      // padded psm row (conflict-free)

// SMEM layout (bytes)
#define SM_B_OFF    0                    // B fp16 [256 n][128 B]        = 32768
#define SM_A_OFF    32768                // A fp16 [128 px][128 B]       = 16384
#define SM_PSM_OFF  49152                // peephole [3][64][132] f32    = 101376
#define SM_HALO_OFF 150528               // halo 2 x [3][18][10] f32     = 4320
#define SM_TOTAL    154848

#define CT_ 512

__global__ void __launch_bounds__(CT_, 1)
fused_mma_kernel(const float* __restrict__ X,
                 const float* __restrict__ Wc, const float* __restrict__ bconv,
                 const float* __restrict__ Wci, const float* __restrict__ Wcf,
                 const float* __restrict__ Wco, float* __restrict__ out) {
    extern __shared__ __align__(1024) char sm[];
    const uint32_t smb = smem_u32(sm);
    float* psm = (float*)(sm + SM_PSM_OFF);
    float* hsm = (float*)(sm + SM_HALO_OFF);    // [slot][ci*180 + rr*10 + cc]

    const int tid  = threadIdx.x;
    const int wid  = tid >> 5;
    const int lane = tid & 31;
    const int mt   = wid & 7;
    const int nh   = wid >> 3;
    const int tile = blockIdx.x;
    const int b    = blockIdx.y;
    const int trow = (tile >> 3) * 16;
    const int tcol = (tile & 7) * 8;

    const float* Xb = X + (size_t)b * 3 * T_ * HW_;

    // ---- prologue: B weights, A const cols, psm (padded) ----
    for (int i = tid; i < 256 * 32; i += CT_) {
        int n = i >> 5;
        int p = i & 31;
        int tile8 = n >> 3;
        int jj    = n & 7;
        int c     = (tile8 >> 1) * 4 + (jj >> 1);
        int gate  = (tile8 & 1) * 2 + (jj & 1);
        int o     = gate * 64 + c;
        float v0 = 0.f, v1 = 0.f;
        if (p < 27) {
            int ci  = p / 9;
            int khw = p - ci * 9;
            v0 = Wc[o * 54 + ci * 18 + khw];
            v1 = Wc[o * 54 + ci * 18 + 9 + khw];
        } else if (p == 27) {
            v0 = bconv[o];
        }
        *(uint32_t*)(sm + SM_B_OFF + sw128((uint32_t)(n * 128 + p * 4))) = f16x2(v1, v0);
    }
    for (int i = tid; i < 128 * 5; i += CT_) {
        int px = i / 5;
        int p  = 27 + (i - px * 5);
        uint32_t v = (p == 27) ? f16x2(0.f, 1.f) : 0u;
        *(uint32_t*)(sm + SM_A_OFF + sw128((uint32_t)(px * 128 + p * 4))) = v;
    }
    for (int i = tid; i < 3 * 64 * 128; i += CT_) {
        int arr = i >> 13;
        int rem = i & 8191;
        int c   = rem >> 7;
        int pl  = rem & 127;
        int hh  = trow + (pl >> 3);
        int ww  = tcol + (pl & 7);
        const float* s = (arr == 0) ? Wci : (arr == 1) ? Wcf : Wco;
        psm[arr * (64 * PSTRIDE) + c * PSTRIDE + pl] = s[c * HW_ + hh * W_ + ww];
    }

    // ---- halo prefetch descriptors (t-invariant) ----
    int h0idx, h0goff; bool h0ok;
    {
        int i  = tid;                   // 0..511 < 540
        int ci = i / 180;
        int rem = i - ci * 180;
        int rr = rem / 10;
        int cc = rem - rr * 10;
        int hh = trow - 1 + rr;
        int ww = tcol - 1 + cc;
        h0ok   = (hh >= 0 && hh < H_ && ww >= 0 && ww < W_);
        h0idx  = i;
        h0goff = ci * (T_ * HW_) + hh * W_ + ww;
    }
    int h1idx = 0, h1goff = 0; bool h1ok = false;
    if (tid < 28) {
        int i  = tid + 512;
        int ci = i / 180;
        int rem = i - ci * 180;
        int rr = rem / 10;
        int cc = rem - rr * 10;
        int hh = trow - 1 + rr;
        int ww = tcol - 1 + cc;
        h1ok   = (hh >= 0 && hh < H_ && ww >= 0 && ww < W_);
        h1idx  = i;
        h1goff = ci * (T_ * HW_) + hh * W_ + ww;
    }
    // stage plane 0 into slot 0, zero slot 1 (t = -1)
    hsm[h0idx] = h0ok ? Xb[h0goff] : 0.f;
    hsm[540 + h0idx] = 0.f;
    if (tid < 28) {
        hsm[h1idx] = h1ok ? Xb[h1goff] : 0.f;
        hsm[540 + h1idx] = 0.f;
    }

    // ---- A-build descriptors (t-invariant): 7 items per thread ----
    int  asoff[7];
    int  aoff[7];
#pragma unroll
    for (int k = 0; k < 7; k++) {
        int i = tid + k * CT_;
        if (i < 128 * 27) {
            int px = i / 27;
            int p  = i - px * 27;
            int ci  = p / 9;
            int khw = p - ci * 9;
            int kh  = khw / 3;
            int kw  = khw - kh * 3;
            asoff[k] = ci * 180 + ((px >> 3) + kh) * 10 + ((px & 7) + kw);
            aoff[k]  = SM_A_OFF + (int)sw128((uint32_t)(px * 128 + p * 4));
        } else {
            asoff[k] = -1;
            aoff[k]  = 0;
        }
    }
    __syncthreads();

    // ---- lane-constant ldmatrix addresses ----
    const int g  = lane >> 3;
    const int r8 = lane & 7;
    const uint32_t cL = (uint32_t)r8 << 4;
    const int rowA = mt * 16 + r8 + 8 * (g & 1);
    const uint32_t dkA = (uint32_t)(g >> 1) * 16;
    const uint32_t aBase = smb + SM_A_OFF + (uint32_t)rowA * 128;
    const int rowB = r8 + 8 * (g >> 1);
    const uint32_t dkB = (uint32_t)(g & 1) * 16;
    const uint32_t bBase = smb + SM_B_OFF + (uint32_t)nh * 16384 + (uint32_t)rowB * 128;

    // ---- recurrence roles ----
    const int q    = lane & 3;
    const int px0  = mt * 16 + (lane >> 2);
    const int px1  = px0 + 8;
    const int hw0  = (trow + (px0 >> 3)) * W_ + tcol + (px0 & 7);
    const int hw1  = (trow + (px1 >> 3)) * W_ + tcol + (px1 & 7);
    const int cb   = nh * 32 + q;

    const float* pb0 = psm + cb * PSTRIDE + px0;   // +v*4*PSTRIDE, +arr*64*PSTRIDE
    const float* pb1 = psm + cb * PSTRIDE + px1;
    float* outp0 = out + ((size_t)b * COUT_ + cb) * (T_ * HW_) + hw0;
    float* outp1 = out + ((size_t)b * COUT_ + cb) * (T_ * HW_) + hw1;

    float C[16];
#pragma unroll
    for (int m = 0; m < 16; m++) C[m] = 0.f;

    for (int t = 0; t < T_; t++) {
        const int buf0 = ((t & 1) ^ 1) * 540;   // x(t-1)
        const int buf1 = (t & 1) * 540;         // x(t)

        // ---- A-build(t): 2 LDS + 1 STS per item, no arithmetic ----
#pragma unroll
        for (int k = 0; k < 7; k++) {
            if (asoff[k] >= 0) {
                float v0 = hsm[buf0 + asoff[k]];
                float v1 = hsm[buf1 + asoff[k]];
                *(uint32_t*)(sm + aoff[k]) = f16x2(v1, v0);
            }
        }
        __syncthreads();

        // ---- prefetch halo plane t+1 (overlaps MMA + recurrence) ----
        float pf0 = 0.f, pf1 = 0.f;
        if (t + 1 < T_) {
            const int toff = (t + 1) * HW_;
            if (h0ok) pf0 = Xb[h0goff + toff];
            if (h1ok) pf1 = Xb[h1goff + toff];
        }

        // ---- MMA + recurrence in 2 N-halves (acc[32] live) ----
        const size_t tof = (size_t)t * HW_;
#pragma unroll
        for (int half = 0; half < 2; half++) {
            float acc[32];
#pragma unroll
            for (int m = 0; m < 32; m++) acc[m] = 0.f;

#pragma unroll
            for (int kc = 0; kc < 4; kc++) {
                uint32_t a0, a1, a2, a3;
                ldmatrix_x4(a0, a1, a2, a3, aBase + (((uint32_t)kc * 32 + dkA) ^ cL));
#pragma unroll
                for (int npl = 0; npl < 4; npl++) {
                    int np = half * 4 + npl;
                    uint32_t b0, b1, b2, b3;
                    ldmatrix_x4(b0, b1, b2, b3,
                                bBase + (uint32_t)np * 2048 + (((uint32_t)kc * 32 + dkB) ^ cL));
                    mma16816(acc + npl * 8,     a0, a1, a2, a3, b0, b1);  // (i,f)
                    mma16816(acc + npl * 8 + 4, a0, a1, a2, a3, b2, b3);  // (g,o)
                }
            }

#pragma unroll
            for (int npl = 0; npl < 4; npl++) {
                const int v = half * 4 + npl;
                const float* A = acc + npl * 8;  // [i0 f0 i1 f1 | g0 o0 g1 o1]
                const float* q0 = pb0 + v * (4 * PSTRIDE);
                const float* q1 = pb1 + v * (4 * PSTRIDE);
                {
                    float Cp = C[2 * v];
                    float ig = sig_fast(A[0] + q0[0] * Cp);
                    float fg = sig_fast(A[1] + q0[64 * PSTRIDE] * Cp);
                    float Cn = fg * Cp + ig * tanh_fast(A[4]);
                    float og = sig_fast(A[5] + q0[128 * PSTRIDE] * Cn);
                    outp0[(size_t)v * (4 * T_ * HW_) + tof] = og * tanh_fast(Cn);
                    C[2 * v] = Cn;
                }
                {
                    float Cp = C[2 * v + 1];
                    float ig = sig_fast(A[2] + q1[0] * Cp);
                    float fg = sig_fast(A[3] + q1[64 * PSTRIDE] * Cp);
                    float Cn = fg * Cp + ig * tanh_fast(A[6]);
                    float og = sig_fast(A[7] + q1[128 * PSTRIDE] * Cn);
                    outp1[(size_t)v * (4 * T_ * HW_) + tof] = og * tanh_fast(Cn);
                    C[2 * v + 1] = Cn;
                }
            }
        }

        // ---- store prefetched halo(t+1) into slot (t+1)&1 ( == buf0 slot) ----
        hsm[buf0 + h0idx] = pf0;
        if (tid < 28) hsm[buf0 + h1idx] = pf1;
        __syncthreads();
    }
}

// ---------------------------------------------------------------------------
// kernel_launch
// ---------------------------------------------------------------------------
extern "C" void kernel_launch(void* const* d_in, const int* in_sizes, int n_in,
                              void* d_out, int out_size) {
    const float* X     = (const float*)d_in[0];
    const float* Wc    = (const float*)d_in[1];
    const float* bconv = (const float*)d_in[2];
    const float* Wci   = (const float*)d_in[3];
    const float* Wcf   = (const float*)d_in[4];
    const float* Wco   = (const float*)d_in[5];
    float* out = (float*)d_out;

    cudaFuncSetAttribute(fused_mma_kernel, cudaFuncAttributeMaxDynamicSharedMemorySize,
                         SM_TOTAL);

    dim3 grid(32, B_);   // 32 tiles x 4 batches = 128 CTAs (one wave)
    fused_mma_kernel<<<grid, CT_, SM_TOTAL>>>(X, Wc, bconv, Wci, Wcf, Wco, out);
}

// round 9
// speedup vs baseline: 5.9664x; 1.1818x over previous
#include <cuda_runtime.h>
#include <cuda_fp16.h>
#include <cstdint>
#include <cstddef>

// ---------------------------------------------------------------------------
// Portable PTX helpers (base sm_103 target: no 'a'-suffix instructions)
// ---------------------------------------------------------------------------
__device__ __forceinline__ uint32_t smem_u32(const void* p) {
    uint32_t a;
    asm("{ .reg .u64 t; cvta.to.shared.u64 t, %1; cvt.u32.u64 %0, t; }"
        : "=r"(a) : "l"(p));
    return a;
}
__device__ __forceinline__ float tanh_fast(float x) {
    float y;
    asm("tanh.approx.f32 %0, %1;" : "=f"(y) : "f"(x));
    return y;
}
__device__ __forceinline__ float sig_fast(float x) {
    return fmaf(0.5f, tanh_fast(0.5f * x), 0.5f);
}
// pack two f32 -> f16x2 {lo, hi}
__device__ __forceinline__ uint32_t f16x2(float hi, float lo) {
    uint32_t r;
    asm("cvt.rn.f16x2.f32 %0, %1, %2;" : "=r"(r) : "f"(hi), "f"(lo));
    return r;
}
__device__ __forceinline__ void ldmatrix_x4(uint32_t& r0, uint32_t& r1,
                                            uint32_t& r2, uint32_t& r3,
                                            uint32_t addr) {
    asm volatile("ldmatrix.sync.aligned.m8n8.x4.shared.b16 {%0,%1,%2,%3}, [%4];"
                 : "=r"(r0), "=r"(r1), "=r"(r2), "=r"(r3) : "r"(addr));
}
__device__ __forceinline__ void mma16816(float* d, uint32_t a0, uint32_t a1,
                                         uint32_t a2, uint32_t a3,
                                         uint32_t b0, uint32_t b1) {
    asm volatile(
        "mma.sync.aligned.m16n8k16.row.col.f32.f16.f16.f32 "
        "{%0,%1,%2,%3}, {%4,%5,%6,%7}, {%8,%9}, {%0,%1,%2,%3};"
        : "+f"(d[0]), "+f"(d[1]), "+f"(d[2]), "+f"(d[3])
        : "r"(a0), "r"(a1), "r"(a2), "r"(a3), "r"(b0), "r"(b1));
}
__device__ __forceinline__ uint32_t sw128(uint32_t off) {
    return off ^ ((off >> 3) & 0x70);
}

// ---------------------------------------------------------------------------
// Problem constants
// ---------------------------------------------------------------------------
#define B_    4
#define T_    32
#define H_    64
#define W_    64
#define COUT_ 64
#define HW_   4096

// K layout: pair p = j = ci*9+kh*3+kw (0..26), halves = kd {t-1, t}.
// Pair 27: A = {1.0, 0}, B = {bias, 0}. Pairs 28..31 zero.
// B row n: tile8=n>>3, jj=n&7 -> cout c=(tile8>>1)*4+(jj>>1), gate=(tile8&1)*2+(jj&1)

// SMEM layout (bytes)
#define SM_B_OFF    0                    // B fp16 [256 n][128 B]   = 32768
#define SM_A_OFF    32768                // A fp16 [128 px][128 B]  = 16384
#define SM_HALO_OFF 49152                // halo 2 x 540 f32        = 4320
#define SM_TOTAL    53472

#define CT_ 512

__global__ void __launch_bounds__(CT_, 1)
fused_mma_kernel(const float* __restrict__ X,
                 const float* __restrict__ Wc, const float* __restrict__ bconv,
                 const float* __restrict__ Wci, const float* __restrict__ Wcf,
                 const float* __restrict__ Wco, float* __restrict__ out) {
    extern __shared__ __align__(1024) char sm[];
    const uint32_t smb = smem_u32(sm);
    float* hsm = (float*)(sm + SM_HALO_OFF);    // [slot][ci*180 + rr*10 + cc]

    const int tid  = threadIdx.x;
    const int wid  = tid >> 5;
    const int lane = tid & 31;
    const int wm   = wid & 3;                   // M-quarter: 32 px
    const int nq   = wid >> 2;                  // N-quarter: 64 gate rows
    const int tile = blockIdx.x;
    const int b    = blockIdx.y;
    const int trow = (tile >> 3) * 16;
    const int tcol = (tile & 7) * 8;

    const float* Xb = X + (size_t)b * 3 * T_ * HW_;

    // ---- prologue: B weights + bias (fp16, SW128), A const cols ----
    for (int i = tid; i < 256 * 32; i += CT_) {
        int n = i >> 5;
        int p = i & 31;
        int tile8 = n >> 3;
        int jj    = n & 7;
        int c     = (tile8 >> 1) * 4 + (jj >> 1);
        int gate  = (tile8 & 1) * 2 + (jj & 1);
        int o     = gate * 64 + c;
        float v0 = 0.f, v1 = 0.f;
        if (p < 27) {
            int ci  = p / 9;
            int khw = p - ci * 9;
            v0 = Wc[o * 54 + ci * 18 + khw];
            v1 = Wc[o * 54 + ci * 18 + 9 + khw];
        } else if (p == 27) {
            v0 = bconv[o];
        }
        *(uint32_t*)(sm + SM_B_OFF + sw128((uint32_t)(n * 128 + p * 4))) = f16x2(v1, v0);
    }
    for (int i = tid; i < 128 * 5; i += CT_) {
        int px = i / 5;
        int p  = 27 + (i - px * 5);
        uint32_t v = (p == 27) ? f16x2(0.f, 1.f) : 0u;
        *(uint32_t*)(sm + SM_A_OFF + sw128((uint32_t)(px * 128 + p * 4))) = v;
    }

    // ---- halo prefetch descriptors (t-invariant) ----
    int h0idx, h0goff; bool h0ok;
    {
        int i  = tid;                   // 0..511 < 540
        int ci = i / 180;
        int rem = i - ci * 180;
        int rr = rem / 10;
        int cc = rem - rr * 10;
        int hh = trow - 1 + rr;
        int ww = tcol - 1 + cc;
        h0ok   = (hh >= 0 && hh < H_ && ww >= 0 && ww < W_);
        h0idx  = i;
        h0goff = ci * (T_ * HW_) + hh * W_ + ww;
    }
    int h1idx = 0, h1goff = 0; bool h1ok = false;
    if (tid < 28) {
        int i  = tid + 512;
        int ci = i / 180;
        int rem = i - ci * 180;
        int rr = rem / 10;
        int cc = rem - rr * 10;
        int hh = trow - 1 + rr;
        int ww = tcol - 1 + cc;
        h1ok   = (hh >= 0 && hh < H_ && ww >= 0 && ww < W_);
        h1idx  = i;
        h1goff = ci * (T_ * HW_) + hh * W_ + ww;
    }
    hsm[h0idx] = h0ok ? Xb[h0goff] : 0.f;     // plane 0 -> slot 0
    hsm[540 + h0idx] = 0.f;                   // t = -1 -> slot 1
    if (tid < 28) {
        hsm[h1idx] = h1ok ? Xb[h1goff] : 0.f;
        hsm[540 + h1idx] = 0.f;
    }

    // ---- A-build descriptors packed: (swizzled A-rel offset << 10) | halo off ----
    uint32_t adesc[7];
#pragma unroll
    for (int k = 0; k < 7; k++) {
        int i = tid + k * CT_;
        if (i < 128 * 27) {
            int px = i / 27;
            int p  = i - px * 27;
            int ci  = p / 9;
            int khw = p - ci * 9;
            int kh  = khw / 3;
            int kw  = khw - kh * 3;
            uint32_t asoff = (uint32_t)(ci * 180 + ((px >> 3) + kh) * 10 + ((px & 7) + kw));
            uint32_t arel  = sw128((uint32_t)(px * 128 + p * 4));
            adesc[k] = (arel << 10) | asoff;
        } else {
            adesc[k] = 0xFFFFFFFFu;
        }
    }

    // ---- peephole params -> fp16 registers ----
    const int q  = lane & 3;
    const int lr = lane >> 2;
    const int r8 = lane & 7;
    const int g  = lane >> 3;
    const int hw0 = (trow + wm * 4) * 64 + tcol + lr;

    __half2 wifh[16];
    __half2 wcoh[8];
    {
        float wcot[16];
#pragma unroll
        for (int m = 0; m < 16; m++) {
            int quarter = m >> 2;
            int krow    = m & 3;
            int c   = (nq * 4 + quarter) * 4 + q;
            int hwm = hw0 + krow * 64;
            wifh[m] = __floats2half2_rn(Wci[c * HW_ + hwm], Wcf[c * HW_ + hwm]);
            wcot[m] = Wco[c * HW_ + hwm];
        }
#pragma unroll
        for (int j = 0; j < 8; j++)
            wcoh[j] = __floats2half2_rn(wcot[2 * j], wcot[2 * j + 1]);
    }
    __syncthreads();

    // ---- lane-constant ldmatrix addresses ----
    const uint32_t cL  = (uint32_t)r8 << 4;
    const uint32_t dkA = (uint32_t)(g >> 1) * 16;
    const uint32_t dkB = (uint32_t)(g & 1) * 16;
    const uint32_t aB0 = smb + SM_A_OFF + (uint32_t)(wm * 32 + r8 + 8 * (g & 1)) * 128;
    const uint32_t aB1 = aB0 + 16 * 128;
    const uint32_t bB  = smb + SM_B_OFF + (uint32_t)(nq * 64 + r8 + 8 * (g >> 1)) * 128;

    // ---- output base pointers (one per quarter) ----
    float* outq[4];
#pragma unroll
    for (int quarter = 0; quarter < 4; quarter++) {
        int c = (nq * 4 + quarter) * 4 + q;
        outq[quarter] = out + ((size_t)(b * COUT_ + c)) * (T_ * HW_) + hw0;
    }

    float C[16];
#pragma unroll
    for (int m = 0; m < 16; m++) C[m] = 0.f;

    for (int t = 0; t < T_; t++) {
        const int buf0 = ((t & 1) ^ 1) * 540;   // x(t-1)
        const int buf1 = (t & 1) * 540;         // x(t)

        // ---- A-build(t) ----
#pragma unroll
        for (int k = 0; k < 7; k++) {
            uint32_t d = adesc[k];
            if (d != 0xFFFFFFFFu) {
                int asoff = (int)(d & 1023);
                float v0 = hsm[buf0 + asoff];
                float v1 = hsm[buf1 + asoff];
                *(uint32_t*)(sm + SM_A_OFF + (d >> 10)) = f16x2(v1, v0);
            }
        }
        __syncthreads();

        // ---- prefetch halo plane t+1 (overlaps MMA + recurrence) ----
        float pf0 = 0.f, pf1 = 0.f;
        if (t + 1 < T_) {
            const int toff = (t + 1) * HW_;
            if (h0ok) pf0 = Xb[h0goff + toff];
            if (h1ok) pf1 = Xb[h1goff + toff];
        }

        // ---- load ALL A fragments for this t (32 regs) ----
        uint32_t af[32];
#pragma unroll
        for (int kc = 0; kc < 4; kc++) {
            uint32_t ko = (((uint32_t)kc * 32) + dkA) ^ cL;
            ldmatrix_x4(af[kc * 8], af[kc * 8 + 1], af[kc * 8 + 2], af[kc * 8 + 3],
                        aB0 + ko);
            ldmatrix_x4(af[kc * 8 + 4], af[kc * 8 + 5], af[kc * 8 + 6], af[kc * 8 + 7],
                        aB1 + ko);
        }

        const size_t tof = (size_t)t * HW_;
#pragma unroll
        for (int quarter = 0; quarter < 4; quarter++) {
            float acc[16];
#pragma unroll
            for (int m = 0; m < 16; m++) acc[m] = 0.f;

            const uint32_t bq = bB + (uint32_t)quarter * 2048;
#pragma unroll
            for (int kc = 0; kc < 4; kc++) {
                uint32_t b0, b1, b2, b3;
                ldmatrix_x4(b0, b1, b2, b3, bq + ((((uint32_t)kc * 32) + dkB) ^ cL));
                mma16816(acc,      af[kc*8],   af[kc*8+1], af[kc*8+2], af[kc*8+3], b0, b1);
                mma16816(acc + 4,  af[kc*8],   af[kc*8+1], af[kc*8+2], af[kc*8+3], b2, b3);
                mma16816(acc + 8,  af[kc*8+4], af[kc*8+5], af[kc*8+6], af[kc*8+7], b0, b1);
                mma16816(acc + 12, af[kc*8+4], af[kc*8+5], af[kc*8+6], af[kc*8+7], b2, b3);
            }

            // ---- recurrence: 4 cells (rows lr, lr+8, lr+16, lr+24; cout fixed) ----
            float* op = outq[quarter] + tof;
#pragma unroll
            for (int krow = 0; krow < 4; krow++) {
                const int m    = quarter * 4 + krow;
                const int base = (krow >> 1) * 8 + (krow & 1) * 2;
                float iv = acc[base];
                float fv = acc[base + 1];
                float gv = acc[base + 4];
                float ov = acc[base + 5];
                float2 wif = __half22float2(wifh[m]);
                float wco  = (krow & 1) ? __high2float(wcoh[m >> 1])
                                        : __low2float(wcoh[m >> 1]);
                float Cp = C[m];
                float ig = sig_fast(iv + wif.x * Cp);
                float fg = sig_fast(fv + wif.y * Cp);
                float Cn = fg * Cp + ig * tanh_fast(gv);
                float og = sig_fast(ov + wco * Cn);
                op[krow * 64] = og * tanh_fast(Cn);
                C[m] = Cn;
            }
        }

        // ---- store prefetched halo(t+1) into slot (t+1)&1 ----
        hsm[buf0 + h0idx] = pf0;
        if (tid < 28) hsm[buf0 + h1idx] = pf1;
        __syncthreads();
    }
}

// ---------------------------------------------------------------------------
// kernel_launch
// ---------------------------------------------------------------------------
extern "C" void kernel_launch(void* const* d_in, const int* in_sizes, int n_in,
                              void* d_out, int out_size) {
    const float* X     = (const float*)d_in[0];
    const float* Wc    = (const float*)d_in[1];
    const float* bconv = (const float*)d_in[2];
    const float* Wci   = (const float*)d_in[3];
    const float* Wcf   = (const float*)d_in[4];
    const float* Wco   = (const float*)d_in[5];
    float* out = (float*)d_out;

    cudaFuncSetAttribute(fused_mma_kernel, cudaFuncAttributeMaxDynamicSharedMemorySize,
                         SM_TOTAL);

    dim3 grid(32, B_);   // 32 tiles x 4 batches = 128 CTAs (one wave)
    fused_mma_kernel<<<grid, CT_, SM_TOTAL>>>(X, Wc, bconv, Wci, Wcf, Wco, out);
}